// round 1
// baseline (speedup 1.0000x reference)
#include <cuda_runtime.h>
#include <cstdint>

// Problem constants (fixed by the reference)
#define BATCH   8192
#define DCONT   1024
#define VCAT    10000
#define NOUT    16
#define VEC     (VCAT / 4)      // 2500 float4 per cat row
#define FULL    0xffffffffu

// Warp layout: g = lane>>2 (0..7) selects which feature within a group-of-8,
// c = lane&3 selects which float4 quarter of the 16 outputs this lane owns.

__device__ __forceinline__ void cat_row(const float4* __restrict__ xr,
                                        const float4* __restrict__ Wcat4,
                                        float4& acc, int& cnt,
                                        int lane, int g, int c) {
    for (int i0 = 0; i0 < VEC; i0 += 128) {
        float4 v[4];
        #pragma unroll
        for (int j = 0; j < 4; j++) {
            int idx = i0 + j * 32 + lane;
            if (idx < VEC) v[j] = __ldg(xr + idx);
            else           v[j] = make_float4(0.f, 0.f, 0.f, 0.f);
        }
        #pragma unroll
        for (int j = 0; j < 4; j++) {
            float4 vv = v[j];
            bool nz = (vv.x != 0.f) | (vv.y != 0.f) | (vv.z != 0.f) | (vv.w != 0.f);
            unsigned m = __ballot_sync(FULL, nz);
            if (m) {
                cnt += (vv.x != 0.f) + (vv.y != 0.f) + (vv.z != 0.f) + (vv.w != 0.f);
                while (m) {
                    int src = __ffs(m) - 1;
                    m &= m - 1;
                    float sx = __shfl_sync(FULL, vv.x, src);
                    float sy = __shfl_sync(FULL, vv.y, src);
                    float sz = __shfl_sync(FULL, vv.z, src);
                    float sw = __shfl_sync(FULL, vv.w, src);
                    int sidx = i0 + j * 32 + src;   // vec index of source lane
                    // Each nonzero component -> add W_cat row (64B broadcast load).
                    if (sx != 0.f) { float4 w = __ldg(Wcat4 + (sidx * 4 + 0) * 4 + c);
                        if (g == 0) { acc.x += w.x; acc.y += w.y; acc.z += w.z; acc.w += w.w; } }
                    if (sy != 0.f) { float4 w = __ldg(Wcat4 + (sidx * 4 + 1) * 4 + c);
                        if (g == 0) { acc.x += w.x; acc.y += w.y; acc.z += w.z; acc.w += w.w; } }
                    if (sz != 0.f) { float4 w = __ldg(Wcat4 + (sidx * 4 + 2) * 4 + c);
                        if (g == 0) { acc.x += w.x; acc.y += w.y; acc.z += w.z; acc.w += w.w; } }
                    if (sw != 0.f) { float4 w = __ldg(Wcat4 + (sidx * 4 + 3) * 4 + c);
                        if (g == 0) { acc.x += w.x; acc.y += w.y; acc.z += w.z; acc.w += w.w; } }
                }
            }
        }
    }
}

__global__ void __launch_bounds__(128)
sparse_feature_linear_kernel(const float* __restrict__ xcont,
                             const float* __restrict__ xcat,
                             const float* __restrict__ Wc,
                             const float* __restrict__ Wcat,
                             const float* __restrict__ bias,
                             float* __restrict__ out) {
    int warp = (blockIdx.x * blockDim.x + threadIdx.x) >> 5;
    int lane = threadIdx.x & 31;
    int g = lane >> 2;
    int c = lane & 3;

    int row0 = warp * 2;
    if (row0 >= BATCH) return;
    int row1 = row0 + 1;

    float4 acc0 = make_float4(0.f, 0.f, 0.f, 0.f);
    float4 acc1 = make_float4(0.f, 0.f, 0.f, 0.f);
    int cnt0 = 0, cnt1 = 0;

    const float4* Wcat4 = reinterpret_cast<const float4*>(Wcat);
    const float4* Wc4   = reinterpret_cast<const float4*>(Wc);

    // ---- categorical branch: stream the 0/1 mask, gather W_cat on nonzeros ----
    cat_row(reinterpret_cast<const float4*>(xcat + (size_t)row0 * VCAT), Wcat4,
            acc0, cnt0, lane, g, c);
    cat_row(reinterpret_cast<const float4*>(xcat + (size_t)row1 * VCAT), Wcat4,
            acc1, cnt1, lane, g, c);

    // ---- continuous branch: dense [1024] x [1024,16] per row ----
    const float* xc0 = xcont + (size_t)row0 * DCONT;
    const float* xc1 = xcont + (size_t)row1 * DCONT;
    for (int jb = 0; jb < DCONT; jb += 32) {
        float xv0 = __ldg(xc0 + jb + lane);
        float xv1 = __ldg(xc1 + jb + lane);
        #pragma unroll
        for (int s = 0; s < 4; s++) {
            int jl = s * 8 + g;                       // feature within this 32-block
            float4 w = __ldg(Wc4 + (jb + jl) * 4 + c); // 512B contiguous per warp
            float a0 = __shfl_sync(FULL, xv0, jl);
            float a1 = __shfl_sync(FULL, xv1, jl);
            acc0.x += a0 * w.x; acc0.y += a0 * w.y; acc0.z += a0 * w.z; acc0.w += a0 * w.w;
            acc1.x += a1 * w.x; acc1.y += a1 * w.y; acc1.z += a1 * w.z; acc1.w += a1 * w.w;
        }
    }

    // ---- reduce partial sums across the 8 g-lanes sharing each quarter c ----
    #pragma unroll
    for (int off = 4; off <= 16; off <<= 1) {
        acc0.x += __shfl_xor_sync(FULL, acc0.x, off);
        acc0.y += __shfl_xor_sync(FULL, acc0.y, off);
        acc0.z += __shfl_xor_sync(FULL, acc0.z, off);
        acc0.w += __shfl_xor_sync(FULL, acc0.w, off);
        acc1.x += __shfl_xor_sync(FULL, acc1.x, off);
        acc1.y += __shfl_xor_sync(FULL, acc1.y, off);
        acc1.z += __shfl_xor_sync(FULL, acc1.z, off);
        acc1.w += __shfl_xor_sync(FULL, acc1.w, off);
    }
    // count reduction over all 32 lanes
    #pragma unroll
    for (int off = 1; off <= 16; off <<= 1) {
        cnt0 += __shfl_xor_sync(FULL, cnt0, off);
        cnt1 += __shfl_xor_sync(FULL, cnt1, off);
    }

    if (lane < 4) {  // g == 0, c == lane
        float4 b4 = __ldg(reinterpret_cast<const float4*>(bias) + c);
        float f0 = (float)(DCONT + cnt0);
        float f1 = (float)(DCONT + cnt1);
        float4 o0, o1;
        o0.x = acc0.x + f0 * b4.x; o0.y = acc0.y + f0 * b4.y;
        o0.z = acc0.z + f0 * b4.z; o0.w = acc0.w + f0 * b4.w;
        o1.x = acc1.x + f1 * b4.x; o1.y = acc1.y + f1 * b4.y;
        o1.z = acc1.z + f1 * b4.z; o1.w = acc1.w + f1 * b4.w;
        reinterpret_cast<float4*>(out)[(size_t)row0 * 4 + c] = o0;
        reinterpret_cast<float4*>(out)[(size_t)row1 * 4 + c] = o1;
    }
}

extern "C" void kernel_launch(void* const* d_in, const int* in_sizes, int n_in,
                              void* d_out, int out_size) {
    const float* xcont = (const float*)d_in[0];   // [8192, 1024]
    const float* xcat  = (const float*)d_in[1];   // [8192, 10000]
    const float* Wc    = (const float*)d_in[2];   // [1024, 16]
    const float* Wcat  = (const float*)d_in[3];   // [10000, 16]
    const float* bias  = (const float*)d_in[4];   // [16]
    float* out = (float*)d_out;                   // [8192, 16]

    // 2 rows per warp, 4 warps per block -> 8192 / 8 = 1024 blocks
    dim3 grid(BATCH / 8);
    dim3 block(128);
    sparse_feature_linear_kernel<<<grid, block>>>(xcont, xcat, Wc, Wcat, bias, out);
}